// round 12
// baseline (speedup 1.0000x reference)
#include <cuda_runtime.h>

// ---------------------------------------------------------------------------
// Problem constants
// ---------------------------------------------------------------------------
#define BATCH   8
#define CH      64        // C_IN == C_OUT == GROUPS == 64  (depthwise)
#define HH      256
#define WW      256
#define KK      3
#define REP_DIM 512
#define ROWS_PER_WARP 8

// ---------------------------------------------------------------------------
// Halo resolution: given the two raw float4s of a 256-wide row, produce the
// 12-entry windowed layout via warp shuffles (interior + seam + reflection).
// r[0..5]  = [left halo, v0.x, v0.y, v0.z, v0.w, right halo]  (w 0..127)
// r[6..11] = [left halo, v1.x, v1.y, v1.z, v1.w, right halo]  (w 128..255)
// ---------------------------------------------------------------------------
__device__ __forceinline__ void resolve_row(float4 v0, float4 v1,
                                            int lane, float* r) {
    const unsigned FULL = 0xffffffffu;
    float up0  = __shfl_up_sync  (FULL, v0.w, 1);   // elem 4j-1   (j>0)
    float dn0  = __shfl_down_sync(FULL, v0.x, 1);   // elem 4j+4   (j<31)
    float b10  = __shfl_sync     (FULL, v1.x, 0);   // elem 128    (seam)
    float up1  = __shfl_up_sync  (FULL, v1.w, 1);   // elem 127+4j (j>0)
    float b031 = __shfl_sync     (FULL, v0.w, 31);  // elem 127    (seam)
    float dn1  = __shfl_down_sync(FULL, v1.x, 1);   // elem 132+4j (j<31)

    // Reflection pad: w=-1 -> w=1 (lane0 own v0.y); w=256 -> w=254 (lane31 own v1.z)
    r[0]  = (lane == 0)  ? v0.y : up0;
    r[1]  = v0.x; r[2] = v0.y; r[3] = v0.z; r[4] = v0.w;
    r[5]  = (lane == 31) ? b10  : dn0;
    r[6]  = (lane == 0)  ? b031 : up1;
    r[7]  = v1.x; r[8] = v1.y; r[9] = v1.z; r[10] = v1.w;
    r[11] = (lane == 31) ? v1.z : dn1;
}

__device__ __forceinline__ void load_row(const float* __restrict__ row,
                                         int lane, float* r) {
    float4 v0 = *reinterpret_cast<const float4*>(row + lane * 4);
    float4 v1 = *reinterpret_cast<const float4*>(row + 128 + lane * 4);
    resolve_row(v0, v1, lane, r);
}

// ---------------------------------------------------------------------------
// Fused kernel, no global synchronization:
//   1) issue RAW priming loads for rows h0-1, h0 (nothing consumes them yet)
//   2) compute this channel's 9 dynamic taps (one dot/warp, smem), hiding the
//      tap latency behind the outstanding priming DRAM loads
//   3) resolve halos, run the rolling 3-row depthwise conv over 8 rows/warp
// grid: (HH/(8*ROWS_PER_WARP), CH, BATCH) = (4, 64, 8), block (32, 8).
// ---------------------------------------------------------------------------
__global__ __launch_bounds__(256)
void sconv_kernel(const float* __restrict__ x,
                  const float* __restrict__ rep,
                  const float* __restrict__ wkey,
                  float* __restrict__ out) {
    const int lane = threadIdx.x;   // 0..31
    const int wid  = threadIdx.y;   // 0..7
    const int c    = blockIdx.y;
    const int b    = blockIdx.z;
    const int h0   = (blockIdx.x * 8 + wid) * ROWS_PER_WARP;

    const float* img = x + ((size_t)(b * CH + c)) * HH * WW;
    float* dst_base  = out + ((size_t)(b * CH + c)) * HH * WW;

    // ---- 1) Raw priming loads (issued now, consumed after phase 2) ----
    const int hm = (h0 == 0) ? 1 : h0 - 1;   // reflect top edge
    const float* rowm = img + (size_t)hm * WW;
    const float* row0 = img + (size_t)h0 * WW;
    float4 pm0 = *reinterpret_cast<const float4*>(rowm + lane * 4);
    float4 pm1 = *reinterpret_cast<const float4*>(rowm + 128 + lane * 4);
    float4 pz0 = *reinterpret_cast<const float4*>(row0 + lane * 4);
    float4 pz1 = *reinterpret_cast<const float4*>(row0 + 128 + lane * 4);

    // ---- 2) Dynamic taps: tap[t] = leaky_relu(rep[b] . w_key[c*9+t]) ----
    __shared__ float s_k[KK * KK];
    {
        const unsigned FULL = 0xffffffffu;
        const float4* r4 = reinterpret_cast<const float4*>(rep + b * REP_DIM);
        const float4* w4 = reinterpret_cast<const float4*>(
            wkey + (size_t)(c * KK * KK + wid) * REP_DIM);
        const float4* w8 = reinterpret_cast<const float4*>(
            wkey + (size_t)(c * KK * KK + 8) * REP_DIM);

        float s = 0.0f, s8 = 0.0f;
        #pragma unroll
        for (int i = 0; i < 4; i++) {
            const int idx = lane + 32 * i;
            const float4 a = r4[idx];
            const float4 w = w4[idx];
            s += a.x * w.x + a.y * w.y + a.z * w.z + a.w * w.w;
            if (wid == 0) {            // warp 0 also covers tap 8
                const float4 v = w8[idx];
                s8 += a.x * v.x + a.y * v.y + a.z * v.z + a.w * v.w;
            }
        }
        #pragma unroll
        for (int o = 16; o > 0; o >>= 1) {
            s  += __shfl_xor_sync(FULL, s, o);
            s8 += __shfl_xor_sync(FULL, s8, o);
        }
        if (lane == 0) {
            s_k[wid] = (s > 0.0f) ? s : 0.1f * s;
            if (wid == 0) s_k[8] = (s8 > 0.0f) ? s8 : 0.1f * s8;
        }
    }
    __syncthreads();

    const float k00 = s_k[0], k01 = s_k[1], k02 = s_k[2];
    const float k10 = s_k[3], k11 = s_k[4], k12 = s_k[5];
    const float k20 = s_k[6], k21 = s_k[7], k22 = s_k[8];

    // ---- 3) Resolve primed rows, then rolling 3-row conv over 8 rows ----
    float R[3][12];
    resolve_row(pm0, pm1, lane, R[0]);
    resolve_row(pz0, pz1, lane, R[1]);

    #pragma unroll
    for (int i = 0; i < ROWS_PER_WARP; i++) {
        const int h  = h0 + i;
        const int hn = (h == HH - 1) ? HH - 2 : h + 1;  // reflect bottom edge
        load_row(img + (size_t)hn * WW, lane, R[(i + 2) % 3]);

        const float* rA = R[i % 3];        // row h-1
        const float* rB = R[(i + 1) % 3];  // row h
        const float* rC = R[(i + 2) % 3];  // row h+1

        float4 oA, oB;
        float* a  = &oA.x;
        float* bb = &oB.x;
        #pragma unroll
        for (int j = 0; j < 4; j++) {
            a[j]  = k00 * rA[j]     + k01 * rA[j + 1] + k02 * rA[j + 2]
                  + k10 * rB[j]     + k11 * rB[j + 1] + k12 * rB[j + 2]
                  + k20 * rC[j]     + k21 * rC[j + 1] + k22 * rC[j + 2];
            bb[j] = k00 * rA[j + 6] + k01 * rA[j + 7] + k02 * rA[j + 8]
                  + k10 * rB[j + 6] + k11 * rB[j + 7] + k12 * rB[j + 8]
                  + k20 * rC[j + 6] + k21 * rC[j + 7] + k22 * rC[j + 8];
        }

        float* dst = dst_base + (size_t)h * WW;
        __stcs(reinterpret_cast<float4*>(dst + lane * 4), oA);
        __stcs(reinterpret_cast<float4*>(dst + 128 + lane * 4), oB);
    }
}

// ---------------------------------------------------------------------------
// Launch — single kernel, single graph node, no device-scope sync.
// Inputs (metadata order): d_in[0]=x [8,64,256,256] f32,
//                          d_in[1]=representation [8,512] f32,
//                          d_in[2]=w_key [576,512] f32
// Output: f32 [8,64,256,256]
// ---------------------------------------------------------------------------
extern "C" void kernel_launch(void* const* d_in, const int* in_sizes, int n_in,
                              void* d_out, int out_size) {
    const float* x    = (const float*)d_in[0];
    const float* rep  = (const float*)d_in[1];
    const float* wkey = (const float*)d_in[2];
    float* out        = (float*)d_out;

    dim3 grid(HH / (8 * ROWS_PER_WARP), CH, BATCH);  // (4, 64, 8) = 2048
    dim3 block(32, 8);
    sconv_kernel<<<grid, block>>>(x, rep, wkey, out);
}

// round 13
// speedup vs baseline: 1.0492x; 1.0492x over previous
#include <cuda_runtime.h>

// ---------------------------------------------------------------------------
// Problem constants
// ---------------------------------------------------------------------------
#define BATCH   8
#define CH      64        // C_IN == C_OUT == GROUPS == 64  (depthwise)
#define HH      256
#define WW      256
#define KK      3
#define REP_DIM 512
#define ROWS_PER_WARP 4

// ---------------------------------------------------------------------------
// Halo resolution: given the two raw float4s of a 256-wide row, produce the
// 12-entry windowed layout via warp shuffles (interior + seam + reflection).
// r[0..5]  = [left halo, v0.x, v0.y, v0.z, v0.w, right halo]  (w 0..127)
// r[6..11] = [left halo, v1.x, v1.y, v1.z, v1.w, right halo]  (w 128..255)
// ---------------------------------------------------------------------------
__device__ __forceinline__ void resolve_row(float4 v0, float4 v1,
                                            int lane, float* r) {
    const unsigned FULL = 0xffffffffu;
    float up0  = __shfl_up_sync  (FULL, v0.w, 1);   // elem 4j-1   (j>0)
    float dn0  = __shfl_down_sync(FULL, v0.x, 1);   // elem 4j+4   (j<31)
    float b10  = __shfl_sync     (FULL, v1.x, 0);   // elem 128    (seam)
    float up1  = __shfl_up_sync  (FULL, v1.w, 1);   // elem 127+4j (j>0)
    float b031 = __shfl_sync     (FULL, v0.w, 31);  // elem 127    (seam)
    float dn1  = __shfl_down_sync(FULL, v1.x, 1);   // elem 132+4j (j<31)

    // Reflection pad: w=-1 -> w=1 (lane0 own v0.y); w=256 -> w=254 (lane31 own v1.z)
    r[0]  = (lane == 0)  ? v0.y : up0;
    r[1]  = v0.x; r[2] = v0.y; r[3] = v0.z; r[4] = v0.w;
    r[5]  = (lane == 31) ? b10  : dn0;
    r[6]  = (lane == 0)  ? b031 : up1;
    r[7]  = v1.x; r[8] = v1.y; r[9] = v1.z; r[10] = v1.w;
    r[11] = (lane == 31) ? v1.z : dn1;
}

__device__ __forceinline__ void load_row(const float* __restrict__ row,
                                         int lane, float* r) {
    float4 v0 = *reinterpret_cast<const float4*>(row + lane * 4);
    float4 v1 = *reinterpret_cast<const float4*>(row + 128 + lane * 4);
    resolve_row(v0, v1, lane, r);
}

// ---------------------------------------------------------------------------
// Fused kernel, no global synchronization:
//   1) issue RAW priming loads for rows h0-1, h0 (nothing consumes them yet)
//   2) compute this channel's 9 dynamic taps (one dot/warp, smem), hiding the
//      tap latency behind the outstanding priming DRAM loads
//   3) resolve halos, run the rolling 3-row depthwise conv
// grid: (HH/(8*ROWS_PER_WARP), CH, BATCH) = (8, 64, 8), block (32, 8).
// __launch_bounds__(256, 6): cap regs at 42 -> 6 blocks/SM (75% occupancy)
// for more outstanding DRAM loads.
// ---------------------------------------------------------------------------
__global__ __launch_bounds__(256, 6)
void sconv_kernel(const float* __restrict__ x,
                  const float* __restrict__ rep,
                  const float* __restrict__ wkey,
                  float* __restrict__ out) {
    const int lane = threadIdx.x;   // 0..31
    const int wid  = threadIdx.y;   // 0..7
    const int c    = blockIdx.y;
    const int b    = blockIdx.z;
    const int h0   = (blockIdx.x * 8 + wid) * ROWS_PER_WARP;

    const float* img = x + ((size_t)(b * CH + c)) * HH * WW;
    float* dst_base  = out + ((size_t)(b * CH + c)) * HH * WW;

    // ---- 1) Raw priming loads (issued now, consumed after phase 2) ----
    const int hm = (h0 == 0) ? 1 : h0 - 1;   // reflect top edge
    const float* rowm = img + (size_t)hm * WW;
    const float* row0 = img + (size_t)h0 * WW;
    float4 pm0 = *reinterpret_cast<const float4*>(rowm + lane * 4);
    float4 pm1 = *reinterpret_cast<const float4*>(rowm + 128 + lane * 4);
    float4 pz0 = *reinterpret_cast<const float4*>(row0 + lane * 4);
    float4 pz1 = *reinterpret_cast<const float4*>(row0 + 128 + lane * 4);

    // ---- 2) Dynamic taps: tap[t] = leaky_relu(rep[b] . w_key[c*9+t]) ----
    __shared__ float s_k[KK * KK];
    {
        const unsigned FULL = 0xffffffffu;
        const float4* r4 = reinterpret_cast<const float4*>(rep + b * REP_DIM);
        const float4* w4 = reinterpret_cast<const float4*>(
            wkey + (size_t)(c * KK * KK + wid) * REP_DIM);
        const float4* w8 = reinterpret_cast<const float4*>(
            wkey + (size_t)(c * KK * KK + 8) * REP_DIM);

        float s = 0.0f, s8 = 0.0f;
        #pragma unroll
        for (int i = 0; i < 4; i++) {
            const int idx = lane + 32 * i;
            const float4 a = r4[idx];
            const float4 w = w4[idx];
            s += a.x * w.x + a.y * w.y + a.z * w.z + a.w * w.w;
            if (wid == 0) {            // warp 0 also covers tap 8
                const float4 v = w8[idx];
                s8 += a.x * v.x + a.y * v.y + a.z * v.z + a.w * v.w;
            }
        }
        #pragma unroll
        for (int o = 16; o > 0; o >>= 1) {
            s  += __shfl_xor_sync(FULL, s, o);
            s8 += __shfl_xor_sync(FULL, s8, o);
        }
        if (lane == 0) {
            s_k[wid] = (s > 0.0f) ? s : 0.1f * s;
            if (wid == 0) s_k[8] = (s8 > 0.0f) ? s8 : 0.1f * s8;
        }
    }
    __syncthreads();

    const float k00 = s_k[0], k01 = s_k[1], k02 = s_k[2];
    const float k10 = s_k[3], k11 = s_k[4], k12 = s_k[5];
    const float k20 = s_k[6], k21 = s_k[7], k22 = s_k[8];

    // ---- 3) Resolve primed rows, then rolling 3-row conv ----
    float R[3][12];
    resolve_row(pm0, pm1, lane, R[0]);
    resolve_row(pz0, pz1, lane, R[1]);

    #pragma unroll
    for (int i = 0; i < ROWS_PER_WARP; i++) {
        const int h  = h0 + i;
        const int hn = (h == HH - 1) ? HH - 2 : h + 1;  // reflect bottom edge
        load_row(img + (size_t)hn * WW, lane, R[(i + 2) % 3]);

        const float* rA = R[i % 3];        // row h-1
        const float* rB = R[(i + 1) % 3];  // row h
        const float* rC = R[(i + 2) % 3];  // row h+1

        float4 oA, oB;
        float* a  = &oA.x;
        float* bb = &oB.x;
        #pragma unroll
        for (int j = 0; j < 4; j++) {
            a[j]  = k00 * rA[j]     + k01 * rA[j + 1] + k02 * rA[j + 2]
                  + k10 * rB[j]     + k11 * rB[j + 1] + k12 * rB[j + 2]
                  + k20 * rC[j]     + k21 * rC[j + 1] + k22 * rC[j + 2];
            bb[j] = k00 * rA[j + 6] + k01 * rA[j + 7] + k02 * rA[j + 8]
                  + k10 * rB[j + 6] + k11 * rB[j + 7] + k12 * rB[j + 8]
                  + k20 * rC[j + 6] + k21 * rC[j + 7] + k22 * rC[j + 8];
        }

        float* dst = dst_base + (size_t)h * WW;
        __stcs(reinterpret_cast<float4*>(dst + lane * 4), oA);
        __stcs(reinterpret_cast<float4*>(dst + 128 + lane * 4), oB);
    }
}

// ---------------------------------------------------------------------------
// Launch — single kernel, single graph node, no device-scope sync.
// Inputs (metadata order): d_in[0]=x [8,64,256,256] f32,
//                          d_in[1]=representation [8,512] f32,
//                          d_in[2]=w_key [576,512] f32
// Output: f32 [8,64,256,256]
// ---------------------------------------------------------------------------
extern "C" void kernel_launch(void* const* d_in, const int* in_sizes, int n_in,
                              void* d_out, int out_size) {
    const float* x    = (const float*)d_in[0];
    const float* rep  = (const float*)d_in[1];
    const float* wkey = (const float*)d_in[2];
    float* out        = (float*)d_out;

    dim3 grid(HH / (8 * ROWS_PER_WARP), CH, BATCH);  // (8, 64, 8) = 4096
    dim3 block(32, 8);
    sconv_kernel<<<grid, block>>>(x, rep, wkey, out);
}

// round 14
// speedup vs baseline: 1.0596x; 1.0099x over previous
#include <cuda_runtime.h>

// ---------------------------------------------------------------------------
// Problem constants
// ---------------------------------------------------------------------------
#define BATCH   8
#define CH      64        // C_IN == C_OUT == GROUPS == 64  (depthwise)
#define HH      256
#define WW      256
#define KK      3
#define REP_DIM 512
#define ROWS_PER_WARP 4

// ---------------------------------------------------------------------------
// Halo resolution: given the two raw float4s of a 256-wide row, produce the
// 12-entry windowed layout via warp shuffles (interior + seam + reflection).
// r[0..5]  = [left halo, v0.x, v0.y, v0.z, v0.w, right halo]  (w 0..127)
// r[6..11] = [left halo, v1.x, v1.y, v1.z, v1.w, right halo]  (w 128..255)
// ---------------------------------------------------------------------------
__device__ __forceinline__ void resolve_row(float4 v0, float4 v1,
                                            int lane, float* r) {
    const unsigned FULL = 0xffffffffu;
    float up0  = __shfl_up_sync  (FULL, v0.w, 1);   // elem 4j-1   (j>0)
    float dn0  = __shfl_down_sync(FULL, v0.x, 1);   // elem 4j+4   (j<31)
    float b10  = __shfl_sync     (FULL, v1.x, 0);   // elem 128    (seam)
    float up1  = __shfl_up_sync  (FULL, v1.w, 1);   // elem 127+4j (j>0)
    float b031 = __shfl_sync     (FULL, v0.w, 31);  // elem 127    (seam)
    float dn1  = __shfl_down_sync(FULL, v1.x, 1);   // elem 132+4j (j<31)

    // Reflection pad: w=-1 -> w=1 (lane0 own v0.y); w=256 -> w=254 (lane31 own v1.z)
    r[0]  = (lane == 0)  ? v0.y : up0;
    r[1]  = v0.x; r[2] = v0.y; r[3] = v0.z; r[4] = v0.w;
    r[5]  = (lane == 31) ? b10  : dn0;
    r[6]  = (lane == 0)  ? b031 : up1;
    r[7]  = v1.x; r[8] = v1.y; r[9] = v1.z; r[10] = v1.w;
    r[11] = (lane == 31) ? v1.z : dn1;
}

// ---------------------------------------------------------------------------
// Fused kernel, no global synchronization:
//   1) issue RAW priming loads for rows h0-1, h0, h0+1 (nothing consumes yet)
//   2) compute this channel's 9 dynamic taps (one dot/warp, smem), hiding the
//      tap latency behind the outstanding priming DRAM loads
//   3) software-pipelined rolling 3-row conv: the raw loads for the row
//      needed in iteration i+1 are issued BEFORE iteration i's data is
//      consumed, so each row load's latency hides behind a full iteration
//      of compute + store.
// grid: (HH/(8*ROWS_PER_WARP), CH, BATCH) = (8, 64, 8), block (32, 8).
// ---------------------------------------------------------------------------
__global__ __launch_bounds__(256)
void sconv_kernel(const float* __restrict__ x,
                  const float* __restrict__ rep,
                  const float* __restrict__ wkey,
                  float* __restrict__ out) {
    const int lane = threadIdx.x;   // 0..31
    const int wid  = threadIdx.y;   // 0..7
    const int c    = blockIdx.y;
    const int b    = blockIdx.z;
    const int h0   = (blockIdx.x * 8 + wid) * ROWS_PER_WARP;

    const float* img = x + ((size_t)(b * CH + c)) * HH * WW;
    float* dst_base  = out + ((size_t)(b * CH + c)) * HH * WW;

    // ---- 1) Raw priming loads (rows h0-1, h0, h0+1) ----
    const int hm = (h0 == 0) ? 1 : h0 - 1;   // reflect top edge
    const float* rowm = img + (size_t)hm * WW;
    const float* row0 = img + (size_t)h0 * WW;
    const float* row1 = img + (size_t)(h0 + 1) * WW;   // h0+1 <= 253, no reflect
    float4 pm0 = *reinterpret_cast<const float4*>(rowm + lane * 4);
    float4 pm1 = *reinterpret_cast<const float4*>(rowm + 128 + lane * 4);
    float4 pz0 = *reinterpret_cast<const float4*>(row0 + lane * 4);
    float4 pz1 = *reinterpret_cast<const float4*>(row0 + 128 + lane * 4);
    float4 pf0 = *reinterpret_cast<const float4*>(row1 + lane * 4);
    float4 pf1 = *reinterpret_cast<const float4*>(row1 + 128 + lane * 4);

    // ---- 2) Dynamic taps: tap[t] = leaky_relu(rep[b] . w_key[c*9+t]) ----
    __shared__ float s_k[KK * KK];
    {
        const unsigned FULL = 0xffffffffu;
        const float4* r4 = reinterpret_cast<const float4*>(rep + b * REP_DIM);
        const float4* w4 = reinterpret_cast<const float4*>(
            wkey + (size_t)(c * KK * KK + wid) * REP_DIM);
        const float4* w8 = reinterpret_cast<const float4*>(
            wkey + (size_t)(c * KK * KK + 8) * REP_DIM);

        float s = 0.0f, s8 = 0.0f;
        #pragma unroll
        for (int i = 0; i < 4; i++) {
            const int idx = lane + 32 * i;
            const float4 a = r4[idx];
            const float4 w = w4[idx];
            s += a.x * w.x + a.y * w.y + a.z * w.z + a.w * w.w;
            if (wid == 0) {            // warp 0 also covers tap 8
                const float4 v = w8[idx];
                s8 += a.x * v.x + a.y * v.y + a.z * v.z + a.w * v.w;
            }
        }
        #pragma unroll
        for (int o = 16; o > 0; o >>= 1) {
            s  += __shfl_xor_sync(FULL, s, o);
            s8 += __shfl_xor_sync(FULL, s8, o);
        }
        if (lane == 0) {
            s_k[wid] = (s > 0.0f) ? s : 0.1f * s;
            if (wid == 0) s_k[8] = (s8 > 0.0f) ? s8 : 0.1f * s8;
        }
    }
    __syncthreads();

    const float k00 = s_k[0], k01 = s_k[1], k02 = s_k[2];
    const float k10 = s_k[3], k11 = s_k[4], k12 = s_k[5];
    const float k20 = s_k[6], k21 = s_k[7], k22 = s_k[8];

    // ---- 3) Pipelined rolling 3-row conv ----
    float R[3][12];
    resolve_row(pm0, pm1, lane, R[0]);
    resolve_row(pz0, pz1, lane, R[1]);
    // pf* currently holds the raw row needed by iteration 0 (row h0+1).

    #pragma unroll
    for (int i = 0; i < ROWS_PER_WARP; i++) {
        // Issue NEXT iteration's raw row load before consuming this one.
        float4 nf0, nf1;
        if (i + 1 < ROWS_PER_WARP) {
            int rr = h0 + i + 2;                 // row for iteration i+1
            if (rr == HH) rr = HH - 2;           // reflect bottom edge
            const float* rn = img + (size_t)rr * WW;
            nf0 = *reinterpret_cast<const float4*>(rn + lane * 4);
            nf1 = *reinterpret_cast<const float4*>(rn + 128 + lane * 4);
        }

        // Consume the prefetched row (loaded one iteration ago).
        resolve_row(pf0, pf1, lane, R[(i + 2) % 3]);

        const float* rA = R[i % 3];        // row h-1
        const float* rB = R[(i + 1) % 3];  // row h
        const float* rC = R[(i + 2) % 3];  // row h+1

        float4 oA, oB;
        float* a  = &oA.x;
        float* bb = &oB.x;
        #pragma unroll
        for (int j = 0; j < 4; j++) {
            a[j]  = k00 * rA[j]     + k01 * rA[j + 1] + k02 * rA[j + 2]
                  + k10 * rB[j]     + k11 * rB[j + 1] + k12 * rB[j + 2]
                  + k20 * rC[j]     + k21 * rC[j + 1] + k22 * rC[j + 2];
            bb[j] = k00 * rA[j + 6] + k01 * rA[j + 7] + k02 * rA[j + 8]
                  + k10 * rB[j + 6] + k11 * rB[j + 7] + k12 * rB[j + 8]
                  + k20 * rC[j + 6] + k21 * rC[j + 7] + k22 * rC[j + 8];
        }

        float* dst = dst_base + (size_t)(h0 + i) * WW;
        __stcs(reinterpret_cast<float4*>(dst + lane * 4), oA);
        __stcs(reinterpret_cast<float4*>(dst + 128 + lane * 4), oB);

        pf0 = nf0;
        pf1 = nf1;
    }
}

// ---------------------------------------------------------------------------
// Launch — single kernel, single graph node, no device-scope sync.
// Inputs (metadata order): d_in[0]=x [8,64,256,256] f32,
//                          d_in[1]=representation [8,512] f32,
//                          d_in[2]=w_key [576,512] f32
// Output: f32 [8,64,256,256]
// ---------------------------------------------------------------------------
extern "C" void kernel_launch(void* const* d_in, const int* in_sizes, int n_in,
                              void* d_out, int out_size) {
    const float* x    = (const float*)d_in[0];
    const float* rep  = (const float*)d_in[1];
    const float* wkey = (const float*)d_in[2];
    float* out        = (float*)d_out;

    dim3 grid(HH / (8 * ROWS_PER_WARP), CH, BATCH);  // (8, 64, 8) = 4096
    dim3 block(32, 8);
    sconv_kernel<<<grid, block>>>(x, rep, wkey, out);
}